// round 15
// baseline (speedup 1.0000x reference)
#include <cuda_runtime.h>
#include <cuda_fp16.h>
#include <cstdint>
#include <cstddef>

// ---------------------------------------------------------------------------
// MultiLatentAttention — B=4, T=4096, C=2048, H=16, D=128, L=64, CHUNK=128
// Only the first 128 tokens per batch feed the latent attention (mask t<=l).
// Reassociated epilogue: AP[b,h] = attn[b,h] @ Wp_h, out = gates @ AP.
// fp16 m16n8k16 mma GEMMs, ldmatrix, 5-stage cp.async, softmax fused into
// the gates-GEMM epilogue. This round: double-buffered fragments (all 12
// LDSM per k-tile issued up front — removes the WAR hazard that serialized
// ks=1 LDSMs behind ks=0 MMAs) + LOADK moved before compute.
// ---------------------------------------------------------------------------

#define SCALE_F 0.08838834764831845f  // 1/sqrt(128)

__device__ __half g_x16[16384 * 2048];     // x rounded to fp16
__device__ __half g_wkvT[4096 * 2048];     // [Wk^T ; Wv^T] fp16, [N][K]
__device__ __half g_wgT[1024 * 2048];      // Wg^T fp16
__device__ float  g_kv128[512 * 4096];     // k (cols 0..2047) | v (2048..4095)
__device__ __half g_gates16[16384 * 1024]; // softmaxed gates fp16
__device__ float  g_attn[64 * 64 * 128];   // attn[bh][l][d]
__device__ __half g_APt[4 * 2048 * 1024];  // per-batch (attn@Wp)^T: [n][h*64+l]

// single dynamic-smem symbol for the whole TU
extern __shared__ char dyn_sm[];

__device__ __forceinline__ uint32_t s2u(const void* p) {
    uint32_t a;
    asm("{ .reg .u64 t; cvta.to.shared.u64 t, %1; cvt.u32.u64 %0, t; }" : "=r"(a) : "l"(p));
    return a;
}
__device__ __forceinline__ void cp16(uint32_t dst, const void* src) {
    asm volatile("cp.async.cg.shared.global [%0], [%1], 16;" :: "r"(dst), "l"(src));
}
#define CP_COMMIT() asm volatile("cp.async.commit_group;" ::: "memory")
#define CP_WAIT3()  asm volatile("cp.async.wait_group 3;" ::: "memory")

#define LDSM4(r, addr)                                                        \
    asm volatile("ldmatrix.sync.aligned.m8n8.x4.shared.b16 {%0,%1,%2,%3}, [%4];" \
                 : "=r"((r)[0]), "=r"((r)[1]), "=r"((r)[2]), "=r"((r)[3])     \
                 : "r"(addr))

#define MMA16(d, a, b0, b1)                                                   \
    asm volatile("mma.sync.aligned.m16n8k16.row.col.f32.f16.f16.f32 "         \
                 "{%0,%1,%2,%3},{%4,%5,%6,%7},{%8,%9},{%0,%1,%2,%3};"         \
                 : "+f"((d)[0]), "+f"((d)[1]), "+f"((d)[2]), "+f"((d)[3])     \
                 : "r"((a)[0]), "r"((a)[1]), "r"((a)[2]), "r"((a)[3]),        \
                   "r"(b0), "r"(b1))

// ---------------------------------------------------------------------------
// fp16 GEMM: C[M,N] = A[M,K] @ BT[N,K]^T. A,BT fp16 row-major.
// Block tile 128x128x32; 8 warps, warp tile 32x64; smem rows padded to 80B.
// 5-stage cp.async pipeline, one __syncthreads per k-tile; LOADK(kt+4)
// issued immediately after the barrier (its stage was freed by that barrier)
// so gmem loads overlap the whole compute phase.
// FUSE==1: row softmax over each 64-col latent group in the epilogue,
// output fp16 (Cv = __half*). FUSE==0: plain fp32 store (Cv = float*).
// Logical A row r -> physical (r/P)*Q + r%P. Batched via blockIdx.z.
// ---------------------------------------------------------------------------
#define NST 5
#define STG_B 20480               // 128*80 (A) + 128*80 (B)
#define GEMM_SMEM (NST * STG_B)   // 102400

template <int FUSE>
__global__ __launch_bounds__(256, 2)
void gemm_f16(const __half* __restrict__ A, const __half* __restrict__ BT,
              void* __restrict__ Cv, int K, int ldc, int P, long Q,
              long long aS, long long bS, long long cS) {
    const uint32_t sb = s2u(dyn_sm);
    const int tid = threadIdx.x, lane = tid & 31, warp = tid >> 5;
    const int wm = warp & 3, wn = warp >> 2;
    const int bn = blockIdx.x, bm = blockIdx.y, bz = blockIdx.z;
    A += aS * bz; BT += bS * bz;

    // gmem fill pointers: this thread loads 16B chunks of rows rr and rr+64
    const int rr = tid >> 2, ch = tid & 3;
    long la0 = (long)bm * 128 + rr, la1 = la0 + 64;
    la0 = (la0 / P) * Q + la0 % P;
    la1 = (la1 / P) * Q + la1 % P;
    const __half* a0p = A + la0 * K + ch * 8;
    const __half* a1p = A + la1 * K + ch * 8;
    const __half* b0p = BT + ((long)bn * 128 + rr) * K + ch * 8;
    const __half* b1p = b0p + (long)64 * K;
    const uint32_t dA0 = rr * 80 + ch * 16, dA1 = dA0 + 64 * 80;
    const uint32_t dB0 = 10240 + dA0, dB1 = 10240 + dA1;

    // ldmatrix per-lane addresses (byte offsets within a stage)
    const int rsel = lane & 15, ksel = (lane >> 4) * 8;  // halves
    const uint32_t aoff0 = (uint32_t)(((wm * 32 + rsel) * 40 + ksel) * 2);
    const uint32_t aoff1 = aoff0 + 16 * 80;
    const int nloc = (lane & 7) + ((lane >> 4) << 3), kadd = lane & 8;
    uint32_t boff[4];
#pragma unroll
    for (int p = 0; p < 4; ++p)
        boff[p] = 10240u + (uint32_t)(((wn * 64 + p * 16 + nloc) * 40 + kadd) * 2);

    float acc[2][8][4];
#pragma unroll
    for (int mt = 0; mt < 2; ++mt)
#pragma unroll
        for (int nt = 0; nt < 8; ++nt)
#pragma unroll
            for (int i = 0; i < 4; ++i) acc[mt][nt][i] = 0.0f;

    const int KT = K >> 5;

#define LOADK(kt)                                                   \
    do {                                                            \
        const uint32_t s_ = sb + ((kt) % NST) * STG_B;              \
        cp16(s_ + dA0, a0p + (kt) * 32);                            \
        cp16(s_ + dA1, a1p + (kt) * 32);                            \
        cp16(s_ + dB0, b0p + (kt) * 32);                            \
        cp16(s_ + dB1, b1p + (kt) * 32);                            \
    } while (0)

    LOADK(0); CP_COMMIT();
    LOADK(1); CP_COMMIT();
    LOADK(2); CP_COMMIT();
    LOADK(3); CP_COMMIT();

    for (int kt = 0; kt < KT; ++kt) {
        CP_WAIT3();
        __syncthreads();
        // Stage (kt+4)%5 == (kt-1)%5 was freed by the barrier above.
        if (kt + 4 < KT) LOADK(kt + 4);
        CP_COMMIT();
        const uint32_t sA = sb + (kt % NST) * STG_B;
        // All 12 LDSMs for this k-tile up front, distinct registers:
        // ks=1 loads overlap ks=0 MMAs (no WAR hazard).
        uint32_t a0[2][4], a1[2][4], b[2][4][4];
        LDSM4(a0[0], sA + aoff0);
        LDSM4(a1[0], sA + aoff1);
        LDSM4(b[0][0], sA + boff[0]);
        LDSM4(b[0][1], sA + boff[1]);
        LDSM4(b[0][2], sA + boff[2]);
        LDSM4(b[0][3], sA + boff[3]);
        LDSM4(a0[1], sA + aoff0 + 32);
        LDSM4(a1[1], sA + aoff1 + 32);
        LDSM4(b[1][0], sA + boff[0] + 32);
        LDSM4(b[1][1], sA + boff[1] + 32);
        LDSM4(b[1][2], sA + boff[2] + 32);
        LDSM4(b[1][3], sA + boff[3] + 32);
#pragma unroll
        for (int ks = 0; ks < 2; ++ks) {
#pragma unroll
            for (int p = 0; p < 4; ++p) {
                MMA16(acc[0][2 * p],     a0[ks], b[ks][p][0], b[ks][p][1]);
                MMA16(acc[0][2 * p + 1], a0[ks], b[ks][p][2], b[ks][p][3]);
                MMA16(acc[1][2 * p],     a1[ks], b[ks][p][0], b[ks][p][1]);
                MMA16(acc[1][2 * p + 1], a1[ks], b[ks][p][2], b[ks][p][3]);
            }
        }
    }

    const int g = lane >> 2, tg = lane & 3;
    if (FUSE) {
        // Row softmax over this warp's 64-col group (cols bn*128 + wn*64 + ..).
        __half* C16 = (__half*)Cv + cS * bz;
#pragma unroll
        for (int mt = 0; mt < 2; ++mt) {
#pragma unroll
            for (int half = 0; half < 2; ++half) {
                const int row = bm * 128 + wm * 32 + mt * 16 + g + half * 8;
                float v[16];
#pragma unroll
                for (int nt = 0; nt < 8; ++nt) {
                    v[2 * nt]     = acc[mt][nt][2 * half]     * SCALE_F;
                    v[2 * nt + 1] = acc[mt][nt][2 * half + 1] * SCALE_F;
                }
                float m = v[0];
#pragma unroll
                for (int i = 1; i < 16; ++i) m = fmaxf(m, v[i]);
                m = fmaxf(m, __shfl_xor_sync(0xffffffffu, m, 1));
                m = fmaxf(m, __shfl_xor_sync(0xffffffffu, m, 2));
                float s = 0.0f;
#pragma unroll
                for (int i = 0; i < 16; ++i) { v[i] = __expf(v[i] - m); s += v[i]; }
                s += __shfl_xor_sync(0xffffffffu, s, 1);
                s += __shfl_xor_sync(0xffffffffu, s, 2);
                const float inv = 1.0f / s;
                __half* rp = C16 + (size_t)row * ldc + bn * 128 + wn * 64 + 2 * tg;
#pragma unroll
                for (int nt = 0; nt < 8; ++nt)
                    *(__half2*)(rp + nt * 8) =
                        __floats2half2_rn(v[2 * nt] * inv, v[2 * nt + 1] * inv);
            }
        }
    } else {
        float* C = (float*)Cv + cS * bz;
#pragma unroll
        for (int mt = 0; mt < 2; ++mt) {
            const int row = bm * 128 + wm * 32 + mt * 16 + g;
#pragma unroll
            for (int nt = 0; nt < 8; ++nt) {
                const int col = bn * 128 + wn * 64 + nt * 8 + 2 * tg;
                *(float2*)(C + (size_t)row * ldc + col) =
                    make_float2(acc[mt][nt][0], acc[mt][nt][1]);
                *(float2*)(C + (size_t)(row + 8) * ldc + col) =
                    make_float2(acc[mt][nt][2], acc[mt][nt][3]);
            }
        }
    }
#undef LOADK
}

// ---------------------------------------------------------------------------
// prep kernels
// ---------------------------------------------------------------------------
__global__ void round_h(const float* __restrict__ in, __half* __restrict__ out) {
    const int i = blockIdx.x * 256 + threadIdx.x;  // quads
    float4 v = ((const float4*)in)[i];
    ((__half2*)out)[2 * i]     = __floats2half2_rn(v.x, v.y);
    ((__half2*)out)[2 * i + 1] = __floats2half2_rn(v.z, v.w);
}

// dst[rowoff + c][r] (fp16, ld=ldd) = src[r][c] (fp32, [R][Cc])
__global__ void transpose_h(const float* __restrict__ W, __half* __restrict__ WT,
                            int R, int Cc, int rowoff, int ldd) {
    __shared__ float t[32][33];
    const int c0 = blockIdx.x * 32, r0 = blockIdx.y * 32;
    const int tx = threadIdx.x & 31, ty = threadIdx.x >> 5;
#pragma unroll
    for (int k = 0; k < 32; k += 8)
        t[ty + k][tx] = W[(size_t)(r0 + ty + k) * Cc + c0 + tx];
    __syncthreads();
#pragma unroll
    for (int k = 0; k < 32; k += 8)
        WT[(size_t)(rowoff + c0 + ty + k) * ldd + r0 + tx] = __float2half_rn(t[tx][ty + k]);
}

// ---------------------------------------------------------------------------
// Latent attention (chunk 0 only): per (b,h) block. kv holds k|v (ld 4096).
// ---------------------------------------------------------------------------
#define ATTN_SMEM_FLOATS (64 * 128 + 128 * 132 + 64 * 128)
#define ATTN_SMEM_BYTES (ATTN_SMEM_FLOATS * 4)

__global__ __launch_bounds__(256)
void attn_kernel(const float* __restrict__ kv, const float* __restrict__ lq,
                 float* __restrict__ attn_out) {
    float* smf = (float*)dyn_sm;
    float* q_s = smf;                 // [64][128]
    float* k_s = smf + 64 * 128;      // [128][132]
    float* w_s = k_s + 128 * 132;     // [64][128]

    const int tid = threadIdx.x;
    const int bh = blockIdx.x;
    const int b = bh >> 4, h = bh & 15;

    for (int i = tid; i < 64 * 128; i += 256) {
        int l = i >> 7, d = i & 127;
        q_s[i] = lq[((size_t)l * 16 + h) * 128 + d];
    }
    const float LOG2_THETA_OVER_HALF = 0.20762050593643188f;  // log2(10000)/64
    for (int p = tid; p < 128 * 64; p += 256) {
        int t = p >> 6, i = p & 63;
        const float* kp = kv + ((size_t)(b * 128 + t)) * 4096 + h * 128 + 2 * i;
        float x0 = kp[0], x1 = kp[1];
        float invf = exp2f(-(float)i * LOG2_THETA_OVER_HALF);
        float ang = (float)t * invf;
        float sn, cs;
        sincosf(ang, &sn, &cs);
        k_s[t * 132 + 2 * i]     = x0 * cs - x1 * sn;
        k_s[t * 132 + 2 * i + 1] = x0 * sn + x1 * cs;
    }
    __syncthreads();

    {
        const int t = tid & 127, lb = tid >> 7;
        const float4* kvv = (const float4*)(k_s + t * 132);
        for (int j = 0; j < 32; ++j) {
            int l = lb + 2 * j;
            const float4* qv = (const float4*)(q_s + l * 128);
            float s = 0.0f;
#pragma unroll
            for (int dd = 0; dd < 32; ++dd) {
                float4 a = qv[dd];
                float4 kk = kvv[dd];
                s += a.x * kk.x + a.y * kk.y + a.z * kk.z + a.w * kk.w;
            }
            s *= SCALE_F;
            if (t > l) s = -1e9f;
            w_s[l * 128 + t] = s;
        }
    }
    __syncthreads();

    {
        const int warp = tid >> 5, lane = tid & 31;
        for (int r = 0; r < 8; ++r) {
            int l = warp * 8 + r;
            float v0 = w_s[l * 128 + lane];
            float v1 = w_s[l * 128 + lane + 32];
            float v2 = w_s[l * 128 + lane + 64];
            float v3 = w_s[l * 128 + lane + 96];
            float m = fmaxf(fmaxf(v0, v1), fmaxf(v2, v3));
#pragma unroll
            for (int o = 16; o > 0; o >>= 1) m = fmaxf(m, __shfl_xor_sync(0xffffffffu, m, o));
            float e0 = __expf(v0 - m), e1 = __expf(v1 - m);
            float e2 = __expf(v2 - m), e3 = __expf(v3 - m);
            float s = e0 + e1 + e2 + e3;
#pragma unroll
            for (int o = 16; o > 0; o >>= 1) s += __shfl_xor_sync(0xffffffffu, s, o);
            float inv = 1.0f / s;
            w_s[l * 128 + lane]      = e0 * inv;
            w_s[l * 128 + lane + 32] = e1 * inv;
            w_s[l * 128 + lane + 64] = e2 * inv;
            w_s[l * 128 + lane + 96] = e3 * inv;
        }
    }
    __syncthreads();

    {
        const int d = tid & 127, lb = tid >> 7;
        float acc[32];
#pragma unroll
        for (int j = 0; j < 32; ++j) acc[j] = 0.0f;
        for (int t = 0; t < 128; ++t) {
            float vv = kv[((size_t)(b * 128 + t)) * 4096 + 2048 + h * 128 + d];
#pragma unroll
            for (int j = 0; j < 32; ++j) acc[j] += w_s[(lb + 2 * j) * 128 + t] * vv;
        }
#pragma unroll
        for (int j = 0; j < 32; ++j)
            attn_out[((size_t)bh * 64 + lb + 2 * j) * 128 + d] = acc[j];
    }
}

// ---------------------------------------------------------------------------
// AP: APt[b][n][h*64+l] = sum_d attn[b,h,l,d] * Wp[h*128+d][n]  (fp16 out)
// Block (ntile of 128, bh). smem: attn^T [128][65] + Wp tile [128][128].
// ---------------------------------------------------------------------------
#define AP_SMEM ((128 * 65 + 128 * 128) * 4)

__global__ __launch_bounds__(256)
void ap_kernel(const float* __restrict__ attn, const float* __restrict__ Wp,
               __half* __restrict__ APt) {
    float* smf = (float*)dyn_sm;
    float* aT = smf;              // [d=128][l stride 65]
    float* wp = smf + 128 * 65;   // [d=128][n=128]

    const int tid = threadIdx.x;
    const int bh = blockIdx.y;
    const int b = bh >> 4, h = bh & 15;
    const int n0 = blockIdx.x * 128;

    for (int i = tid; i < 64 * 128; i += 256) {
        int l = i >> 7, d = i & 127;
        aT[d * 65 + l] = attn[(size_t)bh * 8192 + i];
    }
    for (int i = tid; i < 128 * 128; i += 256) {
        int d = i >> 7, c = i & 127;
        wp[i] = Wp[(size_t)(h * 128 + d) * 2048 + n0 + c];
    }
    __syncthreads();

    const int l = tid & 63, ns = (tid >> 6) * 32;
    float acc[32];
#pragma unroll
    for (int i = 0; i < 32; ++i) acc[i] = 0.0f;
    for (int d = 0; d < 128; ++d) {
        const float a = aT[d * 65 + l];
        const float4* w4 = (const float4*)(wp + d * 128 + ns);
#pragma unroll
        for (int i = 0; i < 8; ++i) {
            float4 w = w4[i];
            acc[4 * i]     += a * w.x;
            acc[4 * i + 1] += a * w.y;
            acc[4 * i + 2] += a * w.z;
            acc[4 * i + 3] += a * w.w;
        }
    }
    __half* dst = APt + (size_t)b * 2048 * 1024 + (size_t)h * 64 + l;
#pragma unroll
    for (int i = 0; i < 32; ++i)
        dst[(size_t)(n0 + ns + i) * 1024] = __float2half_rn(acc[i]);
}

// ---------------------------------------------------------------------------
extern "C" void kernel_launch(void* const* d_in, const int* in_sizes, int n_in,
                              void* d_out, int out_size) {
    const float* x  = (const float*)d_in[0];  // [4,4096,2048]
    const float* lq = (const float*)d_in[1];  // [1,64,16,128]
    const float* Wk = (const float*)d_in[2];  // [2048,2048]
    const float* Wv = (const float*)d_in[3];  // [2048,2048]
    const float* Wg = (const float*)d_in[4];  // [2048,1024]
    const float* Wp = (const float*)d_in[5];  // [2048,2048]
    float* out = (float*)d_out;

    __half *x16, *wkvT, *wgT, *g16, *apt;
    float *kvb, *ab;
    cudaGetSymbolAddress((void**)&x16,  g_x16);
    cudaGetSymbolAddress((void**)&wkvT, g_wkvT);
    cudaGetSymbolAddress((void**)&wgT,  g_wgT);
    cudaGetSymbolAddress((void**)&kvb,  g_kv128);
    cudaGetSymbolAddress((void**)&g16,  g_gates16);
    cudaGetSymbolAddress((void**)&ab,   g_attn);
    cudaGetSymbolAddress((void**)&apt,  g_APt);

    cudaFuncSetAttribute(gemm_f16<0>, cudaFuncAttributeMaxDynamicSharedMemorySize, GEMM_SMEM);
    cudaFuncSetAttribute(gemm_f16<1>, cudaFuncAttributeMaxDynamicSharedMemorySize, GEMM_SMEM);
    cudaFuncSetAttribute(attn_kernel, cudaFuncAttributeMaxDynamicSharedMemorySize,
                         ATTN_SMEM_BYTES);
    cudaFuncSetAttribute(ap_kernel, cudaFuncAttributeMaxDynamicSharedMemorySize, AP_SMEM);

    const int IDP = 1 << 30;  // identity row map

    // prep: x -> fp16; weights -> fp16 transposed ([N][K])
    round_h<<<32768, 256>>>(x, x16);
    transpose_h<<<dim3(64, 64), 256>>>(Wk, wkvT, 2048, 2048, 0, 2048);
    transpose_h<<<dim3(64, 64), 256>>>(Wv, wkvT, 2048, 2048, 2048, 2048);
    transpose_h<<<dim3(32, 64), 256>>>(Wg, wgT, 2048, 1024, 0, 2048);

    // K|V fused GEMM: M=512 (rows (r/128)*4096+r%128), N=4096, K=2048
    gemm_f16<0><<<dim3(32, 4, 1), 256, GEMM_SMEM>>>(x16, wkvT, kvb, 2048, 4096,
                                                    128, 4096, 0, 0, 0);
    // gate logits + fused softmax -> fp16 gates: M=16384, N=1024, K=2048
    gemm_f16<1><<<dim3(8, 128, 1), 256, GEMM_SMEM>>>(x16, wgT, g16, 2048, 1024,
                                                     IDP, 0, 0, 0, 0);
    attn_kernel<<<64, 256, ATTN_SMEM_BYTES>>>(kvb, lq, ab);
    ap_kernel<<<dim3(16, 64), 256, AP_SMEM>>>(ab, Wp, apt);
    // out[b] = gates[b] @ AP[b]: M=4096, N=2048, K=1024, batched over 4
    gemm_f16<0><<<dim3(16, 32, 4), 256, GEMM_SMEM>>>(g16, apt, out, 1024, 2048,
                                                     IDP, 0, 4096LL * 1024, 2048LL * 1024,
                                                     4096LL * 2048);
}

// round 16
// speedup vs baseline: 1.0343x; 1.0343x over previous
#include <cuda_runtime.h>
#include <cuda_fp16.h>
#include <cstdint>
#include <cstddef>

// ---------------------------------------------------------------------------
// MultiLatentAttention — B=4, T=4096, C=2048, H=16, D=128, L=64, CHUNK=128
// Only the first 128 tokens per batch feed the latent attention (mask t<=l).
// Reassociated epilogue: AP[b,h] = attn[b,h] @ Wp_h, out = gates @ AP.
// fp16 m16n8k16 mma GEMMs, ldmatrix, 4-stage cp.async, softmax fused into
// the gates-GEMM epilogue. R16 = R13 schedule (interleaved ks, low regs)
// + LOADK hoisted to right after the barrier (full-compute-phase lead time).
// (R15's fragment double-buffer spilled registers and regressed; reverted.)
// ---------------------------------------------------------------------------

#define SCALE_F 0.08838834764831845f  // 1/sqrt(128)

__device__ __half g_x16[16384 * 2048];     // x rounded to fp16
__device__ __half g_wkvT[4096 * 2048];     // [Wk^T ; Wv^T] fp16, [N][K]
__device__ __half g_wgT[1024 * 2048];      // Wg^T fp16
__device__ float  g_kv128[512 * 4096];     // k (cols 0..2047) | v (2048..4095)
__device__ __half g_gates16[16384 * 1024]; // softmaxed gates fp16
__device__ float  g_attn[64 * 64 * 128];   // attn[bh][l][d]
__device__ __half g_APt[4 * 2048 * 1024];  // per-batch (attn@Wp)^T: [n][h*64+l]

// single dynamic-smem symbol for the whole TU
extern __shared__ char dyn_sm[];

__device__ __forceinline__ uint32_t s2u(const void* p) {
    uint32_t a;
    asm("{ .reg .u64 t; cvta.to.shared.u64 t, %1; cvt.u32.u64 %0, t; }" : "=r"(a) : "l"(p));
    return a;
}
__device__ __forceinline__ void cp16(uint32_t dst, const void* src) {
    asm volatile("cp.async.cg.shared.global [%0], [%1], 16;" :: "r"(dst), "l"(src));
}
#define CP_COMMIT() asm volatile("cp.async.commit_group;" ::: "memory")
#define CP_WAIT2()  asm volatile("cp.async.wait_group 2;" ::: "memory")

#define LDSM4(r, addr)                                                        \
    asm volatile("ldmatrix.sync.aligned.m8n8.x4.shared.b16 {%0,%1,%2,%3}, [%4];" \
                 : "=r"((r)[0]), "=r"((r)[1]), "=r"((r)[2]), "=r"((r)[3])     \
                 : "r"(addr))

#define MMA16(d, a, b0, b1)                                                   \
    asm volatile("mma.sync.aligned.m16n8k16.row.col.f32.f16.f16.f32 "         \
                 "{%0,%1,%2,%3},{%4,%5,%6,%7},{%8,%9},{%0,%1,%2,%3};"         \
                 : "+f"((d)[0]), "+f"((d)[1]), "+f"((d)[2]), "+f"((d)[3])     \
                 : "r"((a)[0]), "r"((a)[1]), "r"((a)[2]), "r"((a)[3]),        \
                   "r"(b0), "r"(b1))

// ---------------------------------------------------------------------------
// fp16 GEMM: C[M,N] = A[M,K] @ BT[N,K]^T. A,BT fp16 row-major.
// Block tile 128x128x32; 8 warps, warp tile 32x64; smem rows padded to 80B.
// 4-stage cp.async pipeline, ONE __syncthreads per k-tile; LOADK(kt+3) is
// issued right after the barrier (its target stage (kt-1)%4 was drained by
// that barrier), giving the loads the whole compute phase of lead time.
// FUSE==1: row softmax over each 64-col latent group in the epilogue,
// output fp16 (Cv = __half*). FUSE==0: plain fp32 store (Cv = float*).
// Logical A row r -> physical (r/P)*Q + r%P. Batched via blockIdx.z.
// ---------------------------------------------------------------------------
#define NST 4
#define STG_B 20480               // 128*80 (A) + 128*80 (B)
#define GEMM_SMEM (NST * STG_B)   // 81920

template <int FUSE>
__global__ __launch_bounds__(256, 2)
void gemm_f16(const __half* __restrict__ A, const __half* __restrict__ BT,
              void* __restrict__ Cv, int K, int ldc, int P, long Q,
              long long aS, long long bS, long long cS) {
    const uint32_t sb = s2u(dyn_sm);
    const int tid = threadIdx.x, lane = tid & 31, warp = tid >> 5;
    const int wm = warp & 3, wn = warp >> 2;
    const int bn = blockIdx.x, bm = blockIdx.y, bz = blockIdx.z;
    A += aS * bz; BT += bS * bz;

    // gmem fill pointers: this thread loads 16B chunks of rows rr and rr+64
    const int rr = tid >> 2, ch = tid & 3;
    long la0 = (long)bm * 128 + rr, la1 = la0 + 64;
    la0 = (la0 / P) * Q + la0 % P;
    la1 = (la1 / P) * Q + la1 % P;
    const __half* a0p = A + la0 * K + ch * 8;
    const __half* a1p = A + la1 * K + ch * 8;
    const __half* b0p = BT + ((long)bn * 128 + rr) * K + ch * 8;
    const __half* b1p = b0p + (long)64 * K;
    const uint32_t dA0 = rr * 80 + ch * 16, dA1 = dA0 + 64 * 80;
    const uint32_t dB0 = 10240 + dA0, dB1 = 10240 + dA1;

    // ldmatrix per-lane addresses (byte offsets within a stage)
    const int rsel = lane & 15, ksel = (lane >> 4) * 8;  // halves
    const uint32_t aoff0 = (uint32_t)(((wm * 32 + rsel) * 40 + ksel) * 2);
    const uint32_t aoff1 = aoff0 + 16 * 80;
    const int nloc = (lane & 7) + ((lane >> 4) << 3), kadd = lane & 8;
    uint32_t boff[4];
#pragma unroll
    for (int p = 0; p < 4; ++p)
        boff[p] = 10240u + (uint32_t)(((wn * 64 + p * 16 + nloc) * 40 + kadd) * 2);

    float acc[2][8][4];
#pragma unroll
    for (int mt = 0; mt < 2; ++mt)
#pragma unroll
        for (int nt = 0; nt < 8; ++nt)
#pragma unroll
            for (int i = 0; i < 4; ++i) acc[mt][nt][i] = 0.0f;

    const int KT = K >> 5;

#define LOADK(kt)                                                   \
    do {                                                            \
        const uint32_t s_ = sb + ((kt) % NST) * STG_B;              \
        cp16(s_ + dA0, a0p + (kt) * 32);                            \
        cp16(s_ + dA1, a1p + (kt) * 32);                            \
        cp16(s_ + dB0, b0p + (kt) * 32);                            \
        cp16(s_ + dB1, b1p + (kt) * 32);                            \
    } while (0)

    LOADK(0); CP_COMMIT();
    LOADK(1); CP_COMMIT();
    LOADK(2); CP_COMMIT();

    for (int kt = 0; kt < KT; ++kt) {
        CP_WAIT2();
        __syncthreads();
        // Stage (kt+3)%4 == (kt-1)%4 was freed by the barrier above.
        if (kt + 3 < KT) LOADK(kt + 3);
        CP_COMMIT();
        const uint32_t sA = sb + (kt % NST) * STG_B;
#pragma unroll
        for (int ks = 0; ks < 2; ++ks) {
            const uint32_t kb = ks * 32;  // 16 halves
            uint32_t a0[4], a1[4], b[4][4];
            LDSM4(a0, sA + aoff0 + kb);
            LDSM4(a1, sA + aoff1 + kb);
#pragma unroll
            for (int p = 0; p < 4; ++p) LDSM4(b[p], sA + boff[p] + kb);
#pragma unroll
            for (int p = 0; p < 4; ++p) {
                MMA16(acc[0][2 * p],     a0, b[p][0], b[p][1]);
                MMA16(acc[0][2 * p + 1], a0, b[p][2], b[p][3]);
                MMA16(acc[1][2 * p],     a1, b[p][0], b[p][1]);
                MMA16(acc[1][2 * p + 1], a1, b[p][2], b[p][3]);
            }
        }
    }

    const int g = lane >> 2, tg = lane & 3;
    if (FUSE) {
        // Row softmax over this warp's 64-col group (cols bn*128 + wn*64 + ..).
        __half* C16 = (__half*)Cv + cS * bz;
#pragma unroll
        for (int mt = 0; mt < 2; ++mt) {
#pragma unroll
            for (int half = 0; half < 2; ++half) {
                const int row = bm * 128 + wm * 32 + mt * 16 + g + half * 8;
                float v[16];
#pragma unroll
                for (int nt = 0; nt < 8; ++nt) {
                    v[2 * nt]     = acc[mt][nt][2 * half]     * SCALE_F;
                    v[2 * nt + 1] = acc[mt][nt][2 * half + 1] * SCALE_F;
                }
                float m = v[0];
#pragma unroll
                for (int i = 1; i < 16; ++i) m = fmaxf(m, v[i]);
                m = fmaxf(m, __shfl_xor_sync(0xffffffffu, m, 1));
                m = fmaxf(m, __shfl_xor_sync(0xffffffffu, m, 2));
                float s = 0.0f;
#pragma unroll
                for (int i = 0; i < 16; ++i) { v[i] = __expf(v[i] - m); s += v[i]; }
                s += __shfl_xor_sync(0xffffffffu, s, 1);
                s += __shfl_xor_sync(0xffffffffu, s, 2);
                const float inv = 1.0f / s;
                __half* rp = C16 + (size_t)row * ldc + bn * 128 + wn * 64 + 2 * tg;
#pragma unroll
                for (int nt = 0; nt < 8; ++nt)
                    *(__half2*)(rp + nt * 8) =
                        __floats2half2_rn(v[2 * nt] * inv, v[2 * nt + 1] * inv);
            }
        }
    } else {
        float* C = (float*)Cv + cS * bz;
#pragma unroll
        for (int mt = 0; mt < 2; ++mt) {
            const int row = bm * 128 + wm * 32 + mt * 16 + g;
#pragma unroll
            for (int nt = 0; nt < 8; ++nt) {
                const int col = bn * 128 + wn * 64 + nt * 8 + 2 * tg;
                *(float2*)(C + (size_t)row * ldc + col) =
                    make_float2(acc[mt][nt][0], acc[mt][nt][1]);
                *(float2*)(C + (size_t)(row + 8) * ldc + col) =
                    make_float2(acc[mt][nt][2], acc[mt][nt][3]);
            }
        }
    }
#undef LOADK
}

// ---------------------------------------------------------------------------
// prep kernels
// ---------------------------------------------------------------------------
__global__ void round_h(const float* __restrict__ in, __half* __restrict__ out) {
    const int i = blockIdx.x * 256 + threadIdx.x;  // quads
    float4 v = ((const float4*)in)[i];
    ((__half2*)out)[2 * i]     = __floats2half2_rn(v.x, v.y);
    ((__half2*)out)[2 * i + 1] = __floats2half2_rn(v.z, v.w);
}

// dst[rowoff + c][r] (fp16, ld=ldd) = src[r][c] (fp32, [R][Cc])
__global__ void transpose_h(const float* __restrict__ W, __half* __restrict__ WT,
                            int R, int Cc, int rowoff, int ldd) {
    __shared__ float t[32][33];
    const int c0 = blockIdx.x * 32, r0 = blockIdx.y * 32;
    const int tx = threadIdx.x & 31, ty = threadIdx.x >> 5;
#pragma unroll
    for (int k = 0; k < 32; k += 8)
        t[ty + k][tx] = W[(size_t)(r0 + ty + k) * Cc + c0 + tx];
    __syncthreads();
#pragma unroll
    for (int k = 0; k < 32; k += 8)
        WT[(size_t)(rowoff + c0 + ty + k) * ldd + r0 + tx] = __float2half_rn(t[tx][ty + k]);
}

// ---------------------------------------------------------------------------
// Latent attention (chunk 0 only): per (b,h) block. kv holds k|v (ld 4096).
// ---------------------------------------------------------------------------
#define ATTN_SMEM_FLOATS (64 * 128 + 128 * 132 + 64 * 128)
#define ATTN_SMEM_BYTES (ATTN_SMEM_FLOATS * 4)

__global__ __launch_bounds__(256)
void attn_kernel(const float* __restrict__ kv, const float* __restrict__ lq,
                 float* __restrict__ attn_out) {
    float* smf = (float*)dyn_sm;
    float* q_s = smf;                 // [64][128]
    float* k_s = smf + 64 * 128;      // [128][132]
    float* w_s = k_s + 128 * 132;     // [64][128]

    const int tid = threadIdx.x;
    const int bh = blockIdx.x;
    const int b = bh >> 4, h = bh & 15;

    for (int i = tid; i < 64 * 128; i += 256) {
        int l = i >> 7, d = i & 127;
        q_s[i] = lq[((size_t)l * 16 + h) * 128 + d];
    }
    const float LOG2_THETA_OVER_HALF = 0.20762050593643188f;  // log2(10000)/64
    for (int p = tid; p < 128 * 64; p += 256) {
        int t = p >> 6, i = p & 63;
        const float* kp = kv + ((size_t)(b * 128 + t)) * 4096 + h * 128 + 2 * i;
        float x0 = kp[0], x1 = kp[1];
        float invf = exp2f(-(float)i * LOG2_THETA_OVER_HALF);
        float ang = (float)t * invf;
        float sn, cs;
        sincosf(ang, &sn, &cs);
        k_s[t * 132 + 2 * i]     = x0 * cs - x1 * sn;
        k_s[t * 132 + 2 * i + 1] = x0 * sn + x1 * cs;
    }
    __syncthreads();

    {
        const int t = tid & 127, lb = tid >> 7;
        const float4* kvv = (const float4*)(k_s + t * 132);
        for (int j = 0; j < 32; ++j) {
            int l = lb + 2 * j;
            const float4* qv = (const float4*)(q_s + l * 128);
            float s = 0.0f;
#pragma unroll
            for (int dd = 0; dd < 32; ++dd) {
                float4 a = qv[dd];
                float4 kk = kvv[dd];
                s += a.x * kk.x + a.y * kk.y + a.z * kk.z + a.w * kk.w;
            }
            s *= SCALE_F;
            if (t > l) s = -1e9f;
            w_s[l * 128 + t] = s;
        }
    }
    __syncthreads();

    {
        const int warp = tid >> 5, lane = tid & 31;
        for (int r = 0; r < 8; ++r) {
            int l = warp * 8 + r;
            float v0 = w_s[l * 128 + lane];
            float v1 = w_s[l * 128 + lane + 32];
            float v2 = w_s[l * 128 + lane + 64];
            float v3 = w_s[l * 128 + lane + 96];
            float m = fmaxf(fmaxf(v0, v1), fmaxf(v2, v3));
#pragma unroll
            for (int o = 16; o > 0; o >>= 1) m = fmaxf(m, __shfl_xor_sync(0xffffffffu, m, o));
            float e0 = __expf(v0 - m), e1 = __expf(v1 - m);
            float e2 = __expf(v2 - m), e3 = __expf(v3 - m);
            float s = e0 + e1 + e2 + e3;
#pragma unroll
            for (int o = 16; o > 0; o >>= 1) s += __shfl_xor_sync(0xffffffffu, s, o);
            float inv = 1.0f / s;
            w_s[l * 128 + lane]      = e0 * inv;
            w_s[l * 128 + lane + 32] = e1 * inv;
            w_s[l * 128 + lane + 64] = e2 * inv;
            w_s[l * 128 + lane + 96] = e3 * inv;
        }
    }
    __syncthreads();

    {
        const int d = tid & 127, lb = tid >> 7;
        float acc[32];
#pragma unroll
        for (int j = 0; j < 32; ++j) acc[j] = 0.0f;
        for (int t = 0; t < 128; ++t) {
            float vv = kv[((size_t)(b * 128 + t)) * 4096 + 2048 + h * 128 + d];
#pragma unroll
            for (int j = 0; j < 32; ++j) acc[j] += w_s[(lb + 2 * j) * 128 + t] * vv;
        }
#pragma unroll
        for (int j = 0; j < 32; ++j)
            attn_out[((size_t)bh * 64 + lb + 2 * j) * 128 + d] = acc[j];
    }
}

// ---------------------------------------------------------------------------
// AP: APt[b][n][h*64+l] = sum_d attn[b,h,l,d] * Wp[h*128+d][n]  (fp16 out)
// Block (ntile of 128, bh). smem: attn^T [128][65] + Wp tile [128][128].
// ---------------------------------------------------------------------------
#define AP_SMEM ((128 * 65 + 128 * 128) * 4)

__global__ __launch_bounds__(256)
void ap_kernel(const float* __restrict__ attn, const float* __restrict__ Wp,
               __half* __restrict__ APt) {
    float* smf = (float*)dyn_sm;
    float* aT = smf;              // [d=128][l stride 65]
    float* wp = smf + 128 * 65;   // [d=128][n=128]

    const int tid = threadIdx.x;
    const int bh = blockIdx.y;
    const int b = bh >> 4, h = bh & 15;
    const int n0 = blockIdx.x * 128;

    for (int i = tid; i < 64 * 128; i += 256) {
        int l = i >> 7, d = i & 127;
        aT[d * 65 + l] = attn[(size_t)bh * 8192 + i];
    }
    for (int i = tid; i < 128 * 128; i += 256) {
        int d = i >> 7, c = i & 127;
        wp[i] = Wp[(size_t)(h * 128 + d) * 2048 + n0 + c];
    }
    __syncthreads();

    const int l = tid & 63, ns = (tid >> 6) * 32;
    float acc[32];
#pragma unroll
    for (int i = 0; i < 32; ++i) acc[i] = 0.0f;
    for (int d = 0; d < 128; ++d) {
        const float a = aT[d * 65 + l];
        const float4* w4 = (const float4*)(wp + d * 128 + ns);
#pragma unroll
        for (int i = 0; i < 8; ++i) {
            float4 w = w4[i];
            acc[4 * i]     += a * w.x;
            acc[4 * i + 1] += a * w.y;
            acc[4 * i + 2] += a * w.z;
            acc[4 * i + 3] += a * w.w;
        }
    }
    __half* dst = APt + (size_t)b * 2048 * 1024 + (size_t)h * 64 + l;
#pragma unroll
    for (int i = 0; i < 32; ++i)
        dst[(size_t)(n0 + ns + i) * 1024] = __float2half_rn(acc[i]);
}

// ---------------------------------------------------------------------------
extern "C" void kernel_launch(void* const* d_in, const int* in_sizes, int n_in,
                              void* d_out, int out_size) {
    const float* x  = (const float*)d_in[0];  // [4,4096,2048]
    const float* lq = (const float*)d_in[1];  // [1,64,16,128]
    const float* Wk = (const float*)d_in[2];  // [2048,2048]
    const float* Wv = (const float*)d_in[3];  // [2048,2048]
    const float* Wg = (const float*)d_in[4];  // [2048,1024]
    const float* Wp = (const float*)d_in[5];  // [2048,2048]
    float* out = (float*)d_out;

    __half *x16, *wkvT, *wgT, *g16, *apt;
    float *kvb, *ab;
    cudaGetSymbolAddress((void**)&x16,  g_x16);
    cudaGetSymbolAddress((void**)&wkvT, g_wkvT);
    cudaGetSymbolAddress((void**)&wgT,  g_wgT);
    cudaGetSymbolAddress((void**)&kvb,  g_kv128);
    cudaGetSymbolAddress((void**)&g16,  g_gates16);
    cudaGetSymbolAddress((void**)&ab,   g_attn);
    cudaGetSymbolAddress((void**)&apt,  g_APt);

    cudaFuncSetAttribute(gemm_f16<0>, cudaFuncAttributeMaxDynamicSharedMemorySize, GEMM_SMEM);
    cudaFuncSetAttribute(gemm_f16<1>, cudaFuncAttributeMaxDynamicSharedMemorySize, GEMM_SMEM);
    cudaFuncSetAttribute(attn_kernel, cudaFuncAttributeMaxDynamicSharedMemorySize,
                         ATTN_SMEM_BYTES);
    cudaFuncSetAttribute(ap_kernel, cudaFuncAttributeMaxDynamicSharedMemorySize, AP_SMEM);

    const int IDP = 1 << 30;  // identity row map

    // prep: x -> fp16; weights -> fp16 transposed ([N][K])
    round_h<<<32768, 256>>>(x, x16);
    transpose_h<<<dim3(64, 64), 256>>>(Wk, wkvT, 2048, 2048, 0, 2048);
    transpose_h<<<dim3(64, 64), 256>>>(Wv, wkvT, 2048, 2048, 2048, 2048);
    transpose_h<<<dim3(32, 64), 256>>>(Wg, wgT, 2048, 1024, 0, 2048);

    // K|V fused GEMM: M=512 (rows (r/128)*4096+r%128), N=4096, K=2048
    gemm_f16<0><<<dim3(32, 4, 1), 256, GEMM_SMEM>>>(x16, wkvT, kvb, 2048, 4096,
                                                    128, 4096, 0, 0, 0);
    // gate logits + fused softmax -> fp16 gates: M=16384, N=1024, K=2048
    gemm_f16<1><<<dim3(8, 128, 1), 256, GEMM_SMEM>>>(x16, wgT, g16, 2048, 1024,
                                                     IDP, 0, 0, 0, 0);
    attn_kernel<<<64, 256, ATTN_SMEM_BYTES>>>(kvb, lq, ab);
    ap_kernel<<<dim3(16, 64), 256, AP_SMEM>>>(ab, Wp, apt);
    // out[b] = gates[b] @ AP[b]: M=4096, N=2048, K=1024, batched over 4
    gemm_f16<0><<<dim3(16, 32, 4), 256, GEMM_SMEM>>>(g16, apt, out, 1024, 2048,
                                                     IDP, 0, 4096LL * 1024, 2048LL * 1024,
                                                     4096LL * 2048);
}